// round 3
// baseline (speedup 1.0000x reference)
#include <cuda_runtime.h>

typedef unsigned long long ull;

#define B_      8
#define SQ_     16
#define H_      16
#define D_      128
#define CACHE_  8192
#define SKV_    16
#define TT      64      // keys per tile
#define KPAD    132     // padded floats per K row (conflict-free LDS.128)
#define NSTAGE  3
#define NTHREADS 512
#define NWARPS  16
#define SCALE   0.08838834764831845f   // 1/sqrt(128)

__device__ __forceinline__ ull f2fma(ull a, ull b, ull c){
    ull d; asm("fma.rn.f32x2 %0, %1, %2, %3;" : "=l"(d) : "l"(a), "l"(b), "l"(c)); return d;
}
__device__ __forceinline__ ull f2mul(ull a, ull b){
    ull d; asm("mul.rn.f32x2 %0, %1, %2;" : "=l"(d) : "l"(a), "l"(b)); return d;
}
__device__ __forceinline__ ull pack2(float x, float y){
    ull d; asm("mov.b64 %0, {%1, %2};" : "=l"(d) : "f"(x), "f"(y)); return d;
}
__device__ __forceinline__ float2 unpack2(ull a){
    float2 r; asm("mov.b64 {%0, %1}, %2;" : "=f"(r.x), "=f"(r.y) : "l"(a)); return r;
}
__device__ __forceinline__ void cp16(void* dst, const void* src){
    unsigned sa = (unsigned)__cvta_generic_to_shared(dst);
    asm volatile("cp.async.cg.shared.global [%0], [%1], 16;" :: "r"(sa), "l"(src));
}

__global__ void __launch_bounds__(NTHREADS, 1)
attn_kernel(const float* __restrict__ qg, const float* __restrict__ kn,
            const float* __restrict__ vn, const float* __restrict__ kc,
            const float* __restrict__ vc, const int* __restrict__ sptr,
            float* __restrict__ outg)
{
    extern __shared__ float smem[];
    float* ks = smem;                              // [NSTAGE][TT][KPAD]
    float* vs = ks + NSTAGE*TT*KPAD;               // [NSTAGE][TT][D_]
    float* pr = vs + NSTAGE*TT*D_;                 // [NWARPS][TT] probs staging

    const int bh = blockIdx.x;
    const int b = bh / H_, h = bh % H_;
    const int start = sptr[0];
    const int ktot = start + SKV_;
    const int ntiles = (ktot + TT - 1) / TT;

    const int tid  = threadIdx.x;
    const int lane = tid & 31;
    const int wid  = tid >> 5;      // warp = query index (16 warps, 16 queries)
    const int jl   = lane & 7;      // key sub-lane (8 keys per group)
    const int qsec = lane >> 3;     // d-section: 32 dims each

    // ---- Q in registers, pre-scaled by 1/sqrt(D): qr[r] covers dims qsec*32+4r..+3
    ull qr_x[8], qr_y[8];
    {
        const ull s2 = pack2(SCALE, SCALE);
        const float* qp = qg + ((b*SQ_ + wid)*H_ + h)*D_ + qsec*32;
        #pragma unroll
        for (int r = 0; r < 8; ++r){
            ulonglong2 qv = *reinterpret_cast<const ulonglong2*>(qp + 4*r);
            qr_x[r] = f2mul(qv.x, s2);
            qr_y[r] = f2mul(qv.y, s2);
        }
    }

    auto load_tile = [&](int t, int buf){
        const int base = t * TT;
        float* kdst = ks + buf*TT*KPAD;
        float* vdst = vs + buf*TT*D_;
        #pragma unroll
        for (int i = 0; i < 4; ++i){
            int c   = tid + i*NTHREADS;      // 2048 16B-chunks per tensor
            int j   = c >> 5;                // key row within tile
            int col = (c & 31) << 2;         // float column
            int s = base + j;
            if (s >= ktot) s = ktot - 1;     // clamp: masked later
            const float *srck, *srcv;
            if (s < start){
                int off = ((b*CACHE_ + s)*H_ + h)*D_ + col;
                srck = kc + off; srcv = vc + off;
            } else {
                int off = ((b*SKV_ + (s-start))*H_ + h)*D_ + col;
                srck = kn + off; srcv = vn + off;
            }
            cp16(kdst + j*KPAD + col, srck);
            cp16(vdst + j*D_   + col, srcv);
        }
        asm volatile("cp.async.commit_group;");
    };

    float m = -1e30f, lsum = 0.f;
    ull a01 = pack2(0.f,0.f), a23 = pack2(0.f,0.f);

    load_tile(0, 0);
    if (ntiles > 1) load_tile(1, 1);

    for (int t = 0; t < ntiles; ++t){
        const int buf = t % NSTAGE;
        if (t + 2 < ntiles){
            load_tile(t+2, (t+2) % NSTAGE);
            asm volatile("cp.async.wait_group 2;");
        } else if (t + 1 < ntiles){
            asm volatile("cp.async.wait_group 1;");
        } else {
            asm volatile("cp.async.wait_group 0;");
        }
        __syncthreads();

        const float* kb  = ks + buf*TT*KPAD;
        const float* vb  = vs + buf*TT*D_;
        const int   base = t * TT;

        // ---- QK^T: lane (qsec,jl) computes 32-dim partials for 8 keys
        float p[8];
        float tm = -1e30f;

        #pragma unroll
        for (int kk = 0; kk < 8; ++kk){
            const int j = kk*8 + jl;
            const float* krow = kb + j*KPAD + qsec*32;
            ull b0 = pack2(0.f,0.f), b1 = pack2(0.f,0.f);
            #pragma unroll
            for (int r = 0; r < 8; ++r){
                ulonglong2 kv = *reinterpret_cast<const ulonglong2*>(krow + 4*r);
                b0 = f2fma(kv.x, qr_x[r], b0);
                b1 = f2fma(kv.y, qr_y[r], b1);
            }
            float2 s0 = unpack2(b0);
            float2 s1 = unpack2(b1);
            float dot = (s0.x + s0.y) + (s1.x + s1.y);
            dot += __shfl_xor_sync(0xffffffffu, dot, 8);   // combine d-sections
            dot += __shfl_xor_sync(0xffffffffu, dot, 16);
            if (base + j >= ktot) dot = -1e30f;
            p[kk] = dot;
            tm = fmaxf(tm, dot);
        }

        // ---- online softmax update (per-warp, keys split over jl)
        tm = fmaxf(tm, __shfl_xor_sync(0xffffffffu, tm, 1));
        tm = fmaxf(tm, __shfl_xor_sync(0xffffffffu, tm, 2));
        tm = fmaxf(tm, __shfl_xor_sync(0xffffffffu, tm, 4));
        float mnew = fmaxf(m, tm);
        float corr = __expf(m - mnew);
        m = mnew;
        float ps = 0.f;
        #pragma unroll
        for (int kk = 0; kk < 8; ++kk){
            float e = __expf(p[kk] - mnew);
            p[kk] = e;
            ps += e;
        }
        ps += __shfl_xor_sync(0xffffffffu, ps, 1);
        ps += __shfl_xor_sync(0xffffffffu, ps, 2);
        ps += __shfl_xor_sync(0xffffffffu, ps, 4);
        lsum = lsum*corr + ps;
        {
            ull c2 = pack2(corr, corr);
            a01 = f2mul(a01, c2);
            a23 = f2mul(a23, c2);
        }

        // ---- stage probs in per-warp smem (replaces 128 shfl broadcasts)
        float* pw = pr + wid*TT;
        if (qsec == 0){
            #pragma unroll
            for (int kk = 0; kk < 8; ++kk)
                pw[kk*8 + jl] = p[kk];
        }
        __syncwarp();

        // ---- PV: lane owns dims lane*4..+3; probs via broadcast LDS.128
        const float* vrow = vb + lane*4;
        #pragma unroll
        for (int jv = 0; jv < TT/4; ++jv){
            float4 p4 = *reinterpret_cast<const float4*>(pw + jv*4);
            #pragma unroll
            for (int u = 0; u < 4; ++u){
                int j = jv*4 + u;
                float pj = (u==0) ? p4.x : (u==1) ? p4.y : (u==2) ? p4.z : p4.w;
                ulonglong2 vv = *reinterpret_cast<const ulonglong2*>(vrow + j*D_);
                ull p2 = pack2(pj, pj);
                a01 = f2fma(vv.x, p2, a01);
                a23 = f2fma(vv.y, p2, a23);
            }
        }
        __syncthreads();   // protect K/V buffers + probs before next tile
    }

    // ---- epilogue: out[b][q][h*128 + d], warp wid handles query wid
    float inv = 1.0f / lsum;
    float2 o0 = unpack2(a01);
    float2 o1 = unpack2(a23);
    float4 o = make_float4(o0.x*inv, o0.y*inv, o1.x*inv, o1.y*inv);
    float* op = outg + (size_t)(b*SQ_ + wid)*(H_*D_) + h*D_ + lane*4;
    *reinterpret_cast<float4*>(op) = o;
}

extern "C" void kernel_launch(void* const* d_in, const int* in_sizes, int n_in,
                              void* d_out, int out_size)
{
    const float* q  = (const float*)d_in[0];
    const float* k  = (const float*)d_in[1];
    const float* v  = (const float*)d_in[2];
    const float* kc = (const float*)d_in[3];
    const float* vc = (const float*)d_in[4];
    const int* sidx = (const int*)d_in[5];

    const size_t smem_bytes =
        (size_t)(NSTAGE*TT*KPAD + NSTAGE*TT*D_ + NWARPS*TT) * sizeof(float); // 203776
    cudaFuncSetAttribute((const void*)attn_kernel,
                         cudaFuncAttributeMaxDynamicSharedMemorySize,
                         (int)smem_bytes);

    attn_kernel<<<B_*H_, NTHREADS, smem_bytes>>>(q, k, v, kc, vc, sidx, (float*)d_out);
}

// round 5
// speedup vs baseline: 1.8308x; 1.8308x over previous
#include <cuda_runtime.h>

typedef unsigned long long ull;

#define B_      8
#define SQ_     16
#define H_      16
#define D_      128
#define CACHE_  8192
#define SKV_    16
#define TT      64      // keys per tile
#define KP      132     // padded floats per K row (conflict-free LDS.128)
#define NSTAGE  3
#define NTHREADS 256
#define NW      8       // 4 query-groups x 2 key-halves
#define SCALE   0.08838834764831845f   // 1/sqrt(128)

__device__ __forceinline__ ull f2fma(ull a, ull b, ull c){
    ull d; asm("fma.rn.f32x2 %0, %1, %2, %3;" : "=l"(d) : "l"(a), "l"(b), "l"(c)); return d;
}
__device__ __forceinline__ ull f2mul(ull a, ull b){
    ull d; asm("mul.rn.f32x2 %0, %1, %2;" : "=l"(d) : "l"(a), "l"(b)); return d;
}
__device__ __forceinline__ ull pack2(float x, float y){
    ull d; asm("mov.b64 %0, {%1, %2};" : "=l"(d) : "f"(x), "f"(y)); return d;
}
__device__ __forceinline__ float2 unpack2(ull a){
    float2 r; asm("mov.b64 {%0, %1}, %2;" : "=f"(r.x), "=f"(r.y) : "l"(a)); return r;
}
__device__ __forceinline__ void cp16(void* dst, const void* src){
    unsigned sa = (unsigned)__cvta_generic_to_shared(dst);
    asm volatile("cp.async.cg.shared.global [%0], [%1], 16;" :: "r"(sa), "l"(src));
}

__global__ void __launch_bounds__(NTHREADS, 1)
attn_kernel(const float* __restrict__ qg, const float* __restrict__ kn,
            const float* __restrict__ vn, const float* __restrict__ kc,
            const float* __restrict__ vc, const int* __restrict__ sptr,
            float* __restrict__ outg)
{
    extern __shared__ float smem[];
    float* ks  = smem;                              // [NSTAGE][TT][KP]
    float* vs  = ks + NSTAGE*TT*KP;                 // [NSTAGE][TT][D_]
    float* prb = vs + NSTAGE*TT*D_;                 // [NW][32*4] prob staging
    float* mrg = prb + NW*128;                      // [4][4][128] acc merge
    float* mls = mrg + 4*4*D_;                      // [64] m/l merge

    const int bh = blockIdx.x;
    const int b = bh / H_, h = bh % H_;
    const int start = sptr[0];
    const int ktot = start + SKV_;
    const int ntiles = (ktot + TT - 1) / TT;

    const int tid  = threadIdx.x;
    const int lane = tid & 31;
    const int wid  = tid >> 5;
    const int jl   = lane & 3;      // key sub-lane (4 keys per kk group)
    const int qsec = lane >> 2;     // d-section: 8 sections of 16 dims
    const int qg4  = wid & 3;       // query group (4 queries)
    const int kh   = wid >> 2;      // key half (32 keys per tile)

    // ---- Q in registers, pre-scaled: qr[qi][r] covers dims qsec*16 + 4r..+3
    ulonglong2 qr[4][4];
    {
        const ull s2 = pack2(SCALE, SCALE);
        #pragma unroll
        for (int qi = 0; qi < 4; ++qi){
            const float* qp = qg + ((b*SQ_ + (qg4*4+qi))*H_ + h)*D_ + qsec*16;
            #pragma unroll
            for (int r = 0; r < 4; ++r){
                ulonglong2 qv = *reinterpret_cast<const ulonglong2*>(qp + 4*r);
                qr[qi][r].x = f2mul(qv.x, s2);
                qr[qi][r].y = f2mul(qv.y, s2);
            }
        }
    }

    auto load_tile = [&](int t, int buf){
        const int base = t * TT;
        float* kdst = ks + buf*TT*KP;
        float* vdst = vs + buf*TT*D_;
        #pragma unroll
        for (int i = 0; i < 8; ++i){
            int c   = tid + i*NTHREADS;      // 2048 16B-chunks per tensor
            int j   = c >> 5;                // key row within tile
            int col = (c & 31) << 2;         // float column
            int s = base + j;
            if (s >= ktot) s = ktot - 1;     // clamp: masked later
            const float *srck, *srcv;
            if (s < start){
                int off = ((b*CACHE_ + s)*H_ + h)*D_ + col;
                srck = kc + off; srcv = vc + off;
            } else {
                int off = ((b*SKV_ + (s-start))*H_ + h)*D_ + col;
                srck = kn + off; srcv = vn + off;
            }
            cp16(kdst + j*KP + col, srck);
            cp16(vdst + j*D_  + col, srcv);
        }
        asm volatile("cp.async.commit_group;");
    };

    float m[4]    = {-1e30f,-1e30f,-1e30f,-1e30f};
    float lsum[4] = {0.f,0.f,0.f,0.f};
    ull a01[4], a23[4];
    #pragma unroll
    for (int qi = 0; qi < 4; ++qi){ a01[qi]=pack2(0.f,0.f); a23[qi]=pack2(0.f,0.f); }

    load_tile(0, 0);
    if (ntiles > 1) load_tile(1, 1);

    float* pw = prb + wid*128;   // this warp's 32 keys x 4 queries

    for (int t = 0; t < ntiles; ++t){
        const int buf = t % NSTAGE;
        if (t + 2 < ntiles){
            load_tile(t+2, (t+2) % NSTAGE);
            asm volatile("cp.async.wait_group 2;");
        } else if (t + 1 < ntiles){
            asm volatile("cp.async.wait_group 1;");
        } else {
            asm volatile("cp.async.wait_group 0;");
        }
        __syncthreads();

        const float* kb  = ks + buf*TT*KP;
        const float* vb  = vs + buf*TT*D_;
        const int   base = t * TT;

        // ---- QK^T: 32 keys (this half), 4 queries, 16 dims per lane
        float p[4][8];
        float tm[4] = {-1e30f,-1e30f,-1e30f,-1e30f};

        #pragma unroll
        for (int kk = 0; kk < 8; ++kk){
            const int j = kh*32 + kk*4 + jl;          // local key row
            const float* krow = kb + j*KP + qsec*16;
            ulonglong2 kt[4];
            #pragma unroll
            for (int r = 0; r < 4; ++r)
                kt[r] = *reinterpret_cast<const ulonglong2*>(krow + 4*r);
            #pragma unroll
            for (int qi = 0; qi < 4; ++qi){
                ull b0 = pack2(0.f,0.f), b1 = pack2(0.f,0.f);
                #pragma unroll
                for (int r = 0; r < 4; ++r){
                    b0 = f2fma(kt[r].x, qr[qi][r].x, b0);
                    b1 = f2fma(kt[r].y, qr[qi][r].y, b1);
                }
                float2 s0 = unpack2(b0);
                float2 s1 = unpack2(b1);
                float dot = (s0.x + s0.y) + (s1.x + s1.y);
                dot += __shfl_xor_sync(0xffffffffu, dot, 4);    // reduce qsec
                dot += __shfl_xor_sync(0xffffffffu, dot, 8);
                dot += __shfl_xor_sync(0xffffffffu, dot, 16);
                if (base + j >= ktot) dot = -1e30f;
                p[qi][kk] = dot;
                tm[qi] = fmaxf(tm[qi], dot);
            }
        }

        // ---- online softmax (per warp over its 32 keys)
        #pragma unroll
        for (int qi = 0; qi < 4; ++qi){
            float v0 = tm[qi];
            v0 = fmaxf(v0, __shfl_xor_sync(0xffffffffu, v0, 1));
            v0 = fmaxf(v0, __shfl_xor_sync(0xffffffffu, v0, 2));
            float mnew = fmaxf(m[qi], v0);
            float corr = __expf(m[qi] - mnew);
            m[qi] = mnew;
            float ps = 0.f;
            #pragma unroll
            for (int kk = 0; kk < 8; ++kk){
                float e = __expf(p[qi][kk] - mnew);
                p[qi][kk] = e;
                ps += e;
            }
            ps += __shfl_xor_sync(0xffffffffu, ps, 1);
            ps += __shfl_xor_sync(0xffffffffu, ps, 2);
            lsum[qi] = lsum[qi]*corr + ps;
            ull c2 = pack2(corr, corr);
            a01[qi] = f2mul(a01[qi], c2);
            a23[qi] = f2mul(a23[qi], c2);
        }

        // ---- stage probs: lanes qsec==0 write [local_key][qi] float4
        if (qsec == 0){
            #pragma unroll
            for (int kk = 0; kk < 8; ++kk){
                float4 e4 = make_float4(p[0][kk], p[1][kk], p[2][kk], p[3][kk]);
                *reinterpret_cast<float4*>(pw + (kk*4 + jl)*4) = e4;
            }
        }
        __syncwarp();

        // ---- PV: this warp's 32 V rows; lane owns dims lane*4..+3
        const float* vrow = vb + kh*32*D_ + lane*4;
        #pragma unroll
        for (int j2 = 0; j2 < 32; ++j2){
            float4 p4 = *reinterpret_cast<const float4*>(pw + j2*4);
            ulonglong2 vv = *reinterpret_cast<const ulonglong2*>(vrow + j2*D_);
            ull p2;
            p2 = pack2(p4.x, p4.x); a01[0]=f2fma(vv.x,p2,a01[0]); a23[0]=f2fma(vv.y,p2,a23[0]);
            p2 = pack2(p4.y, p4.y); a01[1]=f2fma(vv.x,p2,a01[1]); a23[1]=f2fma(vv.y,p2,a23[1]);
            p2 = pack2(p4.z, p4.z); a01[2]=f2fma(vv.x,p2,a01[2]); a23[2]=f2fma(vv.y,p2,a23[2]);
            p2 = pack2(p4.w, p4.w); a01[3]=f2fma(vv.x,p2,a01[3]); a23[3]=f2fma(vv.y,p2,a23[3]);
        }
        __syncthreads();   // protect K/V buffers before next prefetch
    }

    // ---- cross-half merge: warp (qg4, kh=1) publishes, (qg4, kh=0) combines
    if (kh == 1){
        float* ab = mrg + qg4*(4*D_);
        #pragma unroll
        for (int qi = 0; qi < 4; ++qi){
            float2 o0 = unpack2(a01[qi]);
            float2 o1 = unpack2(a23[qi]);
            *reinterpret_cast<float4*>(ab + qi*D_ + lane*4) =
                make_float4(o0.x, o0.y, o1.x, o1.y);
        }
        if (lane == 0){
            #pragma unroll
            for (int qi = 0; qi < 4; ++qi){
                mls[qg4*8 + qi]     = m[qi];
                mls[qg4*8 + qi + 4] = lsum[qi];
            }
        }
    }
    __syncthreads();

    if (kh == 0){
        const float* ab = mrg + qg4*(4*D_);
        #pragma unroll
        for (int qi = 0; qi < 4; ++qi){
            float m2 = mls[qg4*8 + qi];
            float l2 = mls[qg4*8 + qi + 4];
            float mm = fmaxf(m[qi], m2);
            float e1 = __expf(m[qi] - mm);
            float e2 = __expf(m2    - mm);
            float lt = lsum[qi]*e1 + l2*e2;
            float inv = 1.0f / lt;
            float4 a2 = *reinterpret_cast<const float4*>(ab + qi*D_ + lane*4);
            float2 o0 = unpack2(a01[qi]);
            float2 o1 = unpack2(a23[qi]);
            float4 o = make_float4((o0.x*e1 + a2.x*e2)*inv,
                                   (o0.y*e1 + a2.y*e2)*inv,
                                   (o1.x*e1 + a2.z*e2)*inv,
                                   (o1.y*e1 + a2.w*e2)*inv);
            float* op = outg + (size_t)(b*SQ_ + qg4*4 + qi)*(H_*D_) + h*D_ + lane*4;
            *reinterpret_cast<float4*>(op) = o;
        }
    }
}

extern "C" void kernel_launch(void* const* d_in, const int* in_sizes, int n_in,
                              void* d_out, int out_size)
{
    const float* q  = (const float*)d_in[0];
    const float* k  = (const float*)d_in[1];
    const float* v  = (const float*)d_in[2];
    const float* kc = (const float*)d_in[3];
    const float* vc = (const float*)d_in[4];
    const int* sidx = (const int*)d_in[5];

    const size_t smem_bytes =
        (size_t)(NSTAGE*TT*KP + NSTAGE*TT*D_ + NW*128 + 4*4*D_ + 64) * sizeof(float);
    cudaFuncSetAttribute((const void*)attn_kernel,
                         cudaFuncAttributeMaxDynamicSharedMemorySize,
                         (int)smem_bytes);

    attn_kernel<<<B_*H_, NTHREADS, smem_bytes>>>(q, k, v, kc, vc, sidx, (float*)d_out);
}